// round 15
// baseline (speedup 1.0000x reference)
#include <cuda_runtime.h>
#include <cuda_fp16.h>
#include <math.h>
#include <stdint.h>

#define Tdim 4096
#define Hdim 2048
#define Idim 1024
#define Edim 8
#define CAP  9216   // 8192 assignments + 8*128 padding

// ---------------- device scratch ----------------
__device__ __half g_w1f[(size_t)Edim * 2 * Idim * Hdim];
__device__ __half g_w2f[(size_t)Edim * Hdim * Idim];
__device__ __half g_xf[(size_t)Tdim * Hdim];
__device__ __half g_hf[(size_t)CAP * Idim];
__device__ __half g_yh[(size_t)CAP * Hdim];
__device__ int   g_tok[CAP];
__device__ float g_gate[CAP];
__device__ int   g_cnt[Edim];
__device__ int   g_off[Edim + 1];
__device__ int   g_fill[Edim];
__device__ int   g_eidx[Tdim * 2];
__device__ float g_gates[Tdim * 2];
__device__ int   g_slot[Tdim * 2];

// ---------------- PTX helpers (plain sm_80-era PTX only) ----------------
__device__ __forceinline__ uint32_t su32(const void* p) {
    uint32_t a;
    asm("{ .reg .u64 t; cvta.to.shared.u64 t, %1; cvt.u32.u64 %0, t; }" : "=r"(a) : "l"(p));
    return a;
}
__device__ __forceinline__ void cpa16(uint32_t dst, const void* src, uint32_t sz) {
    asm volatile("cp.async.cg.shared.global [%0], [%1], 16, %2;\n"
                 :: "r"(dst), "l"(src), "r"(sz) : "memory");
}
__device__ __forceinline__ void ldsm4(uint32_t a, uint32_t& r0, uint32_t& r1,
                                      uint32_t& r2, uint32_t& r3) {
    asm volatile("ldmatrix.sync.aligned.m8n8.x4.shared.b16 {%0,%1,%2,%3}, [%4];"
                 : "=r"(r0), "=r"(r1), "=r"(r2), "=r"(r3) : "r"(a));
}
__device__ __forceinline__ void mma16816(float* d, const uint32_t* a, const uint32_t* b) {
    asm volatile("mma.sync.aligned.m16n8k16.row.col.f32.f16.f16.f32 "
                 "{%0,%1,%2,%3}, {%4,%5,%6,%7}, {%8,%9}, {%0,%1,%2,%3};"
                 : "+f"(d[0]), "+f"(d[1]), "+f"(d[2]), "+f"(d[3])
                 : "r"(a[0]), "r"(a[1]), "r"(a[2]), "r"(a[3]), "r"(b[0]), "r"(b[1]));
}

// SMEM stage layout: 2 matrices (A, B), 128 rows x 64 halfs (128B) + 16B pad = 144B stride
// THREE pipeline stages -> one __syncthreads per K-chunk.
#define ROWB 144
#define MATB (128 * ROWB)        // 18432
#define A_OF 0
#define B_OF MATB
#define STAGEB (2 * MATB)        // 36864
#define NSTAGE 3
#define SMEM_SZ (NSTAGE * STAGEB)  // 110592 (108 KB) -> 2 CTAs/SM = 216 KB <= 228 KB
// ---------------- init ----------------
__global__ void init_kernel() {
    int i = blockIdx.x * blockDim.x + threadIdx.x;
    if (i < CAP)  { g_tok[i] = -1; g_gate[i] = 0.f; }
    if (i < Edim) g_cnt[i] = 0;
}

// ---------------- fp32 -> fp16, 8 elems/thread ----------------
__global__ void conv_half_kernel(const float* __restrict__ s,
                                 __half* __restrict__ d, size_t n) {
    size_t i = ((size_t)blockIdx.x * 256 + threadIdx.x) * 8;
    if (i >= n) return;
    float4 v0 = *(const float4*)(s + i);
    float4 v1 = *(const float4*)(s + i + 4);
    __half2 h0 = __floats2half2_rn(v0.x, v0.y);
    __half2 h1 = __floats2half2_rn(v0.z, v0.w);
    __half2 h2 = __floats2half2_rn(v1.x, v1.y);
    __half2 h3 = __floats2half2_rn(v1.z, v1.w);
    uint4 o;
    o.x = *(uint32_t*)&h0; o.y = *(uint32_t*)&h1;
    o.z = *(uint32_t*)&h2; o.w = *(uint32_t*)&h3;
    *(uint4*)(d + i) = o;
}

// ---------------- router ----------------
__global__ void router_kernel(const float* __restrict__ x,
                              const float* __restrict__ rw) {
    const int t   = blockIdx.x;
    const int tid = threadIdx.x;
    float acc[Edim];
#pragma unroll
    for (int e = 0; e < Edim; e++) acc[e] = 0.f;
    const float* xr = x + (size_t)t * Hdim;
    for (int h = tid; h < Hdim; h += 256) {
        float xv = xr[h];
#pragma unroll
        for (int e = 0; e < Edim; e++)
            acc[e] = fmaf(xv, rw[e * Hdim + h], acc[e]);
    }
#pragma unroll
    for (int e = 0; e < Edim; e++)
#pragma unroll
        for (int o = 16; o > 0; o >>= 1)
            acc[e] += __shfl_down_sync(0xffffffffu, acc[e], o);
    __shared__ float s[8][Edim];
    int w = tid >> 5, l = tid & 31;
    if (l == 0)
#pragma unroll
        for (int e = 0; e < Edim; e++) s[w][e] = acc[e];
    __syncthreads();
    if (tid == 0) {
        float logit[Edim];
#pragma unroll
        for (int e = 0; e < Edim; e++) {
            float v = 0.f;
#pragma unroll
            for (int ww = 0; ww < 8; ww++) v += s[ww][e];
            logit[e] = v;
        }
        float m = logit[0];
#pragma unroll
        for (int e = 1; e < Edim; e++) m = fmaxf(m, logit[e]);
        float p[Edim]; float sum = 0.f;
#pragma unroll
        for (int e = 0; e < Edim; e++) { p[e] = expf(logit[e] - m); sum += p[e]; }
        float inv = 1.f / sum;
#pragma unroll
        for (int e = 0; e < Edim; e++) p[e] *= inv;
        int i0 = 0; float p0 = p[0];
#pragma unroll
        for (int e = 1; e < Edim; e++) if (p[e] > p0) { p0 = p[e]; i0 = e; }
        int i1 = -1; float p1 = -1.f;
#pragma unroll
        for (int e = 0; e < Edim; e++)
            if (e != i0 && p[e] > p1) { p1 = p[e]; i1 = e; }
        g_eidx[t * 2 + 0] = i0;  g_gates[t * 2 + 0] = p0;
        g_eidx[t * 2 + 1] = i1;  g_gates[t * 2 + 1] = p1;
        atomicAdd(&g_cnt[i0], 1);
        atomicAdd(&g_cnt[i1], 1);
    }
}

__global__ void offsets_kernel() {
    g_off[0] = 0;
#pragma unroll
    for (int e = 0; e < Edim; e++) {
        g_off[e + 1] = g_off[e] + ((g_cnt[e] + 127) & ~127);
        g_fill[e] = 0;
    }
}

__global__ void scatter_kernel() {
    int t = blockIdx.x * blockDim.x + threadIdx.x;
    if (t >= Tdim) return;
#pragma unroll
    for (int k = 0; k < 2; k++) {
        int e = g_eidx[t * 2 + k];
        int pos = g_off[e] + atomicAdd(&g_fill[e], 1);
        g_tok[pos]  = t;
        g_gate[pos] = g_gates[t * 2 + k];
        g_slot[t * 2 + k] = pos;
    }
}

// ================= GEMM1: up = gather(x) @ w1^T (fp16 mma), SwiGLU*gate -> g_hf =================
__global__ void __launch_bounds__(256, 2) gemm1_kernel() {
    extern __shared__ __align__(128) char smem[];
    __shared__ int   toks[128];
    __shared__ float sgate[128];
    const uint32_t sb = su32(smem);
    const int tid = threadIdx.x, lane = tid & 31, wid = tid >> 5;
    const int wm = (wid & 1) * 64, wn = (wid >> 1) * 32;
    const int bm = blockIdx.x * 128, bn = blockIdx.y * 128;
    if (bm >= g_off[Edim]) return;
    int e = 0;
#pragma unroll
    for (int i = 1; i < Edim; i++) if (bm >= g_off[i]) e = i;
    if (tid < 128) { toks[tid] = g_tok[bm + tid]; sgate[tid] = g_gate[bm + tid]; }
    __syncthreads();

    const __half* w1_b = g_w1f + ((size_t)(e * 2 * Idim) + bn) * Hdim;

    auto load_stage = [&](int kc, int s) {
        const uint32_t base = sb + s * STAGEB;
        const int k0 = kc * 64;
#pragma unroll
        for (int i = 0; i < 4; i++) {
            int idx = tid + i * 256;
            int r = idx >> 3, c = idx & 7;
            int t = toks[r];
            uint32_t sz = (t >= 0) ? 16u : 0u;
            size_t tt = (t >= 0) ? (size_t)t : 0;
            uint32_t dof = r * ROWB + c * 16;
            cpa16(base + A_OF + dof, g_xf + tt * Hdim + k0 + c * 8, sz);
            cpa16(base + B_OF + dof, w1_b + (size_t)r * Hdim + k0 + c * 8, 16u);
        }
        asm volatile("cp.async.commit_group;" ::: "memory");
    };

    float acc[4][4][4];
#pragma unroll
    for (int a = 0; a < 4; a++)
#pragma unroll
        for (int b = 0; b < 4; b++)
#pragma unroll
            for (int c = 0; c < 4; c++) acc[a][b][c] = 0.f;

    const uint32_t a_off = (lane & 15) * ROWB + (lane >> 4) * 16;
    const uint32_t b_off = (((lane >> 4) << 3) | (lane & 7)) * ROWB + ((lane >> 3) & 1) * 16;

    const int NT = Hdim / 64;
    load_stage(0, 0);
    load_stage(1, 1);
    for (int kc = 0; kc < NT; kc++) {
        int s = kc % NSTAGE;
        if (kc + 1 < NT) asm volatile("cp.async.wait_group 1;" ::: "memory");
        else             asm volatile("cp.async.wait_group 0;" ::: "memory");
        __syncthreads();
        if (kc + 2 < NT) load_stage(kc + 2, (kc + 2) % NSTAGE);
        const uint32_t stg = sb + s * STAGEB;
#pragma unroll
        for (int p = 0; p < 4; p++) {
            uint32_t Bv[8];
#pragma unroll
            for (int n2 = 0; n2 < 2; n2++) {
                uint32_t ba = stg + B_OF + (wn + n2 * 16) * ROWB + p * 32 + b_off;
                ldsm4(ba, Bv[n2 * 4 + 0], Bv[n2 * 4 + 1], Bv[n2 * 4 + 2], Bv[n2 * 4 + 3]);
            }
#pragma unroll
            for (int mt = 0; mt < 4; mt++) {
                uint32_t av[4];
                uint32_t aa = stg + A_OF + (wm + mt * 16) * ROWB + p * 32 + a_off;
                ldsm4(aa, av[0], av[1], av[2], av[3]);
#pragma unroll
                for (int nt = 0; nt < 4; nt++)
                    mma16816(acc[mt][nt], av, &Bv[nt * 2]);
            }
        }
    }

    // epilogue: gate * u * silu(g) -> fp16
    const int g = lane >> 2, tg = lane & 3;
#pragma unroll
    for (int mt = 0; mt < 4; mt++) {
        int r0 = wm + mt * 16 + g;
        int slot0 = bm + r0;
        float gate0 = sgate[r0], gate1 = sgate[r0 + 8];
#pragma unroll
        for (int nt = 0; nt < 4; nt++) {
            int hcol = (bn >> 1) + (wn >> 1) + nt * 4 + tg;
            float gv0 = acc[mt][nt][0], uv0 = acc[mt][nt][1];
            float gv1 = acc[mt][nt][2], uv1 = acc[mt][nt][3];
            float h0 = gate0 * uv0 * (gv0 / (1.f + __expf(-gv0)));
            float h1 = gate1 * uv1 * (gv1 / (1.f + __expf(-gv1)));
            g_hf[(size_t)slot0 * Idim + hcol]       = __float2half(h0);
            g_hf[(size_t)(slot0 + 8) * Idim + hcol] = __float2half(h1);
        }
    }
}

// ================= GEMM2: y = h @ w2^T (fp16 mma) -> g_yh (fp16) =================
__global__ void __launch_bounds__(256, 2) gemm2_kernel() {
    extern __shared__ __align__(128) char smem[];
    const uint32_t sb = su32(smem);
    const int tid = threadIdx.x, lane = tid & 31, wid = tid >> 5;
    const int wm = (wid & 1) * 64, wn = (wid >> 1) * 32;
    const int bm = blockIdx.x * 128, bn = blockIdx.y * 128;
    if (bm >= g_off[Edim]) return;
    int e = 0;
#pragma unroll
    for (int i = 1; i < Edim; i++) if (bm >= g_off[i]) e = i;

    const __half* w2_b = g_w2f + ((size_t)(e * Hdim) + bn) * Idim;

    auto load_stage = [&](int kc, int s) {
        const uint32_t base = sb + s * STAGEB;
        const int k0 = kc * 64;
#pragma unroll
        for (int i = 0; i < 4; i++) {
            int idx = tid + i * 256;
            int r = idx >> 3, c = idx & 7;
            uint32_t dof = r * ROWB + c * 16;
            cpa16(base + A_OF + dof, g_hf + (size_t)(bm + r) * Idim + k0 + c * 8, 16u);
            cpa16(base + B_OF + dof, w2_b + (size_t)r * Idim + k0 + c * 8, 16u);
        }
        asm volatile("cp.async.commit_group;" ::: "memory");
    };

    float acc[4][4][4];
#pragma unroll
    for (int a = 0; a < 4; a++)
#pragma unroll
        for (int b = 0; b < 4; b++)
#pragma unroll
            for (int c = 0; c < 4; c++) acc[a][b][c] = 0.f;

    const uint32_t a_off = (lane & 15) * ROWB + (lane >> 4) * 16;
    const uint32_t b_off = (((lane >> 4) << 3) | (lane & 7)) * ROWB + ((lane >> 3) & 1) * 16;

    const int NT = Idim / 64;
    load_stage(0, 0);
    load_stage(1, 1);
    for (int kc = 0; kc < NT; kc++) {
        int s = kc % NSTAGE;
        if (kc + 1 < NT) asm volatile("cp.async.wait_group 1;" ::: "memory");
        else             asm volatile("cp.async.wait_group 0;" ::: "memory");
        __syncthreads();
        if (kc + 2 < NT) load_stage(kc + 2, (kc + 2) % NSTAGE);
        const uint32_t stg = sb + s * STAGEB;
#pragma unroll
        for (int p = 0; p < 4; p++) {
            uint32_t Bv[8];
#pragma unroll
            for (int n2 = 0; n2 < 2; n2++) {
                uint32_t ba = stg + B_OF + (wn + n2 * 16) * ROWB + p * 32 + b_off;
                ldsm4(ba, Bv[n2 * 4 + 0], Bv[n2 * 4 + 1], Bv[n2 * 4 + 2], Bv[n2 * 4 + 3]);
            }
#pragma unroll
            for (int mt = 0; mt < 4; mt++) {
                uint32_t av[4];
                uint32_t aa = stg + A_OF + (wm + mt * 16) * ROWB + p * 32 + a_off;
                ldsm4(aa, av[0], av[1], av[2], av[3]);
#pragma unroll
                for (int nt = 0; nt < 4; nt++)
                    mma16816(acc[mt][nt], av, &Bv[nt * 2]);
            }
        }
    }

    // epilogue: write y rows as fp16 (half2 per thread per row)
    const int g = lane >> 2, tg = lane & 3;
#pragma unroll
    for (int mt = 0; mt < 4; mt++) {
        int slot0 = bm + wm + mt * 16 + g;
#pragma unroll
        for (int nt = 0; nt < 4; nt++) {
            int col = bn + wn + nt * 8 + 2 * tg;
            *(__half2*)(g_yh + (size_t)slot0 * Hdim + col) =
                __floats2half2_rn(acc[mt][nt][0], acc[mt][nt][1]);
            *(__half2*)(g_yh + (size_t)(slot0 + 8) * Hdim + col) =
                __floats2half2_rn(acc[mt][nt][2], acc[mt][nt][3]);
        }
    }
}

// ---------------- combine: out[t] = y[slot0] + y[slot1] (fp16 y, fp32 out) ----------------
__global__ void combine_kernel(float* __restrict__ out) {
    int i = blockIdx.x * 256 + threadIdx.x;   // per 4 outputs
    int t  = i / (Hdim / 4);
    int c4 = i % (Hdim / 4);
    int s0 = g_slot[t * 2], s1 = g_slot[t * 2 + 1];
    uint2 ar = *(const uint2*)(g_yh + (size_t)s0 * Hdim + c4 * 4);
    uint2 br = *(const uint2*)(g_yh + (size_t)s1 * Hdim + c4 * 4);
    float2 a0 = __half22float2(*(__half2*)&ar.x);
    float2 a1 = __half22float2(*(__half2*)&ar.y);
    float2 b0 = __half22float2(*(__half2*)&br.x);
    float2 b1 = __half22float2(*(__half2*)&br.y);
    *(float4*)(out + (size_t)t * Hdim + c4 * 4) =
        make_float4(a0.x + b0.x, a0.y + b0.y, a1.x + b1.x, a1.y + b1.y);
}

// ---------------- launch ----------------
extern "C" void kernel_launch(void* const* d_in, const int* in_sizes, int n_in,
                              void* d_out, int out_size) {
    const float* x  = (const float*)d_in[0];
    const float* rw = (const float*)d_in[1];
    const float* w1 = (const float*)d_in[2];
    const float* w2 = (const float*)d_in[3];
    float* out = (float*)d_out;

    cudaFuncSetAttribute(gemm1_kernel, cudaFuncAttributeMaxDynamicSharedMemorySize, SMEM_SZ);
    cudaFuncSetAttribute(gemm2_kernel, cudaFuncAttributeMaxDynamicSharedMemorySize, SMEM_SZ);

    __half *xf, *w1f, *w2f;
    cudaGetSymbolAddress((void**)&xf,  g_xf);
    cudaGetSymbolAddress((void**)&w1f, g_w1f);
    cudaGetSymbolAddress((void**)&w2f, g_w2f);

    init_kernel<<<(CAP + 255) / 256, 256>>>();
    {
        size_t n = (size_t)Tdim * Hdim;
        conv_half_kernel<<<(unsigned)((n / 8 + 255) / 256), 256>>>(x, xf, n);
    }
    {
        size_t n = (size_t)Edim * 2 * Idim * Hdim;
        conv_half_kernel<<<(unsigned)((n / 8 + 255) / 256), 256>>>(w1, w1f, n);
    }
    {
        size_t n = (size_t)Edim * Hdim * Idim;
        conv_half_kernel<<<(unsigned)((n / 8 + 255) / 256), 256>>>(w2, w2f, n);
    }
    router_kernel<<<Tdim, 256>>>(x, rw);
    offsets_kernel<<<1, 1>>>();
    scatter_kernel<<<(Tdim + 255) / 256, 256>>>();

    dim3 g1(CAP / 128, (2 * Idim) / 128);
    gemm1_kernel<<<g1, 256, SMEM_SZ>>>();
    dim3 g2(CAP / 128, Hdim / 128);
    gemm2_kernel<<<g2, 256, SMEM_SZ>>>();
    combine_kernel<<<(Tdim * Hdim / 4) / 256, 256>>>(out);
}